// round 3
// baseline (speedup 1.0000x reference)
#include <cuda_runtime.h>

// C3 sparse-connectivity conv, 5x5 VALID, fp32, f32x2-packed FMA.
// x: [32,6,512,512] f32, weight: [16,6,5,5] f32, bias: [16] f32
// out: [32,16,508,508] f32
//
// Block: 128(w) x 8(h) output tile, all 16 output channels, one batch image.
// 256 threads: warp = output row, lane -> 4 consecutive x pixels.
// Accumulators packed {p0,p1},{p2,p3} -> fma.rn.f32x2.
// Weights PRE-SPLATTED in smem as {w,w} pairs so the FFMA2 b-operand comes
// straight from LDS (no per-FMA mov.b64 splat on the alu pipe).

#define OW 508
#define OH 508
#define IW 512
#define IH 512
#define TILE_W 128
#define TILE_H 8
#define IN_W 132   // TILE_W + 4
#define IN_H 12    // TILE_H + 4

// smem layout (bytes)
#define S_IN_FLOATS (6 * IN_H * IN_W)        // 9504 floats = 38016 B
#define S_W2_OFF    (S_IN_FLOATS)            // float index; 38016 B -> 16B aligned
#define S_W2_PAIRS  (6 * 10 * 5 * 6)         // 1800 float2 (kx row padded 5->6 = 48B stride)
#define S_B_OFF     (S_W2_OFF + 2 * S_W2_PAIRS)
#define SMEM_BYTES  ((S_B_OFF + 16) * 4)     // 52480 B

__constant__ int d_OC[6][10] = {
    {0, 4, 5, 6, 9, 10, 11, 12, 14, 15},
    {0, 1, 5, 6, 7, 10, 11, 12, 13, 15},
    {0, 1, 2, 6, 7, 8, 11, 13, 14, 15},
    {1, 2, 3, 6, 7, 8, 9, 12, 14, 15},
    {2, 3, 4, 7, 8, 9, 10, 12, 13, 15},
    {3, 4, 5, 8, 9, 10, 11, 13, 14, 15}};

__device__ __forceinline__ unsigned long long pack2(float lo, float hi) {
    unsigned long long r;
    asm("mov.b64 %0, {%1, %2};" : "=l"(r) : "f"(lo), "f"(hi));
    return r;
}
__device__ __forceinline__ void unpack2(unsigned long long v, float& lo, float& hi) {
    asm("mov.b64 {%0, %1}, %2;" : "=f"(lo), "=f"(hi) : "l"(v));
}
// d += a * b (packed fp32 x2) — only explicit PTX emits FFMA2.
__device__ __forceinline__ void ffma2(unsigned long long& d,
                                      unsigned long long a,
                                      unsigned long long b) {
    asm("fma.rn.f32x2 %0, %1, %2, %0;" : "+l"(d) : "l"(a), "l"(b));
}

__global__ void __launch_bounds__(256)
c3_kernel(const float* __restrict__ x,
          const float* __restrict__ wgt,
          const float* __restrict__ bias,
          float* __restrict__ out)
{
    extern __shared__ float smem[];
    float*  s_in = smem;                       // [6][IN_H][IN_W]
    float2* s_w2 = (float2*)(smem + S_W2_OFF); // [ic][j][ky][6] pairs {w,w}
    float*  s_b  = smem + S_B_OFF;             // [16]

    const int tid = threadIdx.x;
    const int x0 = blockIdx.x * TILE_W;
    const int y0 = blockIdx.y * TILE_H;
    const int b  = blockIdx.z;

    // ---- load input tile (OOB -> 0; OOB only feeds skipped outputs) ----
    const float* xb = x + (size_t)b * 6 * IH * IW;
    for (int i = tid; i < 6 * IN_H * IN_W; i += 256) {
        int c   = i / (IN_H * IN_W);
        int r   = (i / IN_W) % IN_H;
        int col = i % IN_W;
        int gy = y0 + r, gx = x0 + col;
        float v = 0.0f;
        if (gy < IH && gx < IW) v = __ldg(&xb[(c * IH + gy) * IW + gx]);
        s_in[(c * IN_H + r) * IN_W + col] = v;
    }
    // ---- repack sparse weights, pre-splatted as {w,w} ----
    for (int i = tid; i < 1500; i += 256) {
        int ic = i / 250;
        int jj = (i / 25) % 10;
        int k  = i % 25;
        int ky = k / 5, kx = k % 5;
        int oc = d_OC[ic][jj];
        float w = __ldg(&wgt[((oc * 6 + ic) * 5 + ky) * 5 + kx]);
        s_w2[((ic * 10 + jj) * 5 + ky) * 6 + kx] = make_float2(w, w);
    }
    if (tid < 16) s_b[tid] = __ldg(&bias[tid]);
    __syncthreads();

    const int wid  = tid >> 5;       // output row within tile
    const int lane = tid & 31;
    const int lx   = lane * 4;       // output x offset within tile

    unsigned long long acc[16][2];   // [oc][half]: {p0,p1},{p2,p3}
#pragma unroll
    for (int oc = 0; oc < 16; ++oc) {
        unsigned long long bv = pack2(s_b[oc], s_b[oc]);
        acc[oc][0] = bv;
        acc[oc][1] = bv;
    }

    constexpr int OC_CT[6][10] = {
        {0, 4, 5, 6, 9, 10, 11, 12, 14, 15},
        {0, 1, 5, 6, 7, 10, 11, 12, 13, 15},
        {0, 1, 2, 6, 7, 8, 11, 13, 14, 15},
        {1, 2, 3, 6, 7, 8, 9, 12, 14, 15},
        {2, 3, 4, 7, 8, 9, 10, 12, 13, 15},
        {3, 4, 5, 8, 9, 10, 11, 13, 14, 15}};

#pragma unroll
    for (int ic = 0; ic < 6; ++ic) {
#pragma unroll 1
        for (int ky = 0; ky < 5; ++ky) {
            // 8-float sliding window for 4 pixels x 5 taps
            const float* rp = &s_in[(ic * IN_H + wid + ky) * IN_W + lx];
            float4 va = *reinterpret_cast<const float4*>(rp);
            float4 vb = *reinterpret_cast<const float4*>(rp + 4);
            float v[8];
            v[0] = va.x; v[1] = va.y; v[2] = va.z; v[3] = va.w;
            v[4] = vb.x; v[5] = vb.y; v[6] = vb.z; v[7] = vb.w;
            unsigned long long P[7];   // P[k] = {v[k], v[k+1]}
#pragma unroll
            for (int k = 0; k < 7; ++k) P[k] = pack2(v[k], v[k + 1]);

#pragma unroll
            for (int j = 0; j < 10; ++j) {
                const int oc = OC_CT[ic][j];
                const float2* wp = &s_w2[((ic * 10 + j) * 5 + ky) * 6];
                // 5 splatted pairs: 2x LDS.128 + 1x LDS.64
                ulonglong2 w01 = *reinterpret_cast<const ulonglong2*>(wp);
                ulonglong2 w23 = *reinterpret_cast<const ulonglong2*>(wp + 2);
                unsigned long long w4 =
                    *reinterpret_cast<const unsigned long long*>(wp + 4);
                ffma2(acc[oc][0], P[0], w01.x);
                ffma2(acc[oc][1], P[2], w01.x);
                ffma2(acc[oc][0], P[1], w01.y);
                ffma2(acc[oc][1], P[3], w01.y);
                ffma2(acc[oc][0], P[2], w23.x);
                ffma2(acc[oc][1], P[4], w23.x);
                ffma2(acc[oc][0], P[3], w23.y);
                ffma2(acc[oc][1], P[5], w23.y);
                ffma2(acc[oc][0], P[4], w4);
                ffma2(acc[oc][1], P[6], w4);
            }
        }
    }

    // ---- store: float4 per oc (OW=508 divisible by 4) ----
    const int oy = y0 + wid;
    const int ox = x0 + lx;
    if (oy < OH && ox < OW) {
#pragma unroll
        for (int oc = 0; oc < 16; ++oc) {
            float4 r;
            unpack2(acc[oc][0], r.x, r.y);
            unpack2(acc[oc][1], r.z, r.w);
            *reinterpret_cast<float4*>(
                out + (((size_t)b * 16 + oc) * OH + oy) * OW + ox) = r;
        }
    }
}

extern "C" void kernel_launch(void* const* d_in, const int* in_sizes, int n_in,
                              void* d_out, int out_size)
{
    const float* x    = (const float*)d_in[0];  // [32,6,512,512]
    const float* wgt  = (const float*)d_in[1];  // [16,6,5,5]
    const float* bias = (const float*)d_in[2];  // [16]
    float* out = (float*)d_out;                 // [32,16,508,508]

    cudaFuncSetAttribute(c3_kernel,
                         cudaFuncAttributeMaxDynamicSharedMemorySize,
                         SMEM_BYTES);

    dim3 grid((OW + TILE_W - 1) / TILE_W,       // 4
              (OH + TILE_H - 1) / TILE_H,       // 64
              32);                              // batch
    c3_kernel<<<grid, 256, SMEM_BYTES>>>(x, wgt, bias, out);
}

// round 5
// speedup vs baseline: 1.0159x; 1.0159x over previous
#include <cuda_runtime.h>

// C3 sparse-connectivity conv, 5x5 VALID, fp32, f32x2-packed FMA.
// x: [32,6,512,512] f32, weight: [16,6,5,5] f32, bias: [16] f32
// out: [32,16,508,508] f32
//
// Block: 128(w) x 4(h) output tile, one batch image. 256 threads = 8 warps.
// Warp = (row 0..3, oc-group 0..1): each warp computes 1 output row x 8 output
// channels. OC groups balanced by edge count (31 / 29 of 60).
// Accumulators packed {p0,p1},{p2,p3} -> fma.rn.f32x2; weights pre-splatted
// {w,w} in smem so the FFMA2 b-operand comes straight from LDS.

#define OW 508
#define OH 508
#define IW 512
#define IH 512
#define TILE_W 128
#define TILE_H 4
#define IN_W 132   // TILE_W + 4
#define IN_H 8     // TILE_H + 4

// ---- edge tables: 60 (ic,oc) edges, group0 = edges 0..30, group1 = 31..59 ----
// group0 ocs {0,1,2,6,7,8,9,15} (31 edges), group1 ocs {3,4,5,10,11,12,13,14} (29)
__constant__ signed char E_IC[60] = {
    0,0,0,0, 1,1,1,1,1, 2,2,2,2,2,2,2, 3,3,3,3,3,3,3, 4,4,4,4,4, 5,5,5,
    0,0,0,0,0,0, 1,1,1,1,1, 2,2,2, 3,3,3, 4,4,4,4,4, 5,5,5,5,5,5,5};
__constant__ signed char E_OC[60] = {
    0,6,9,15, 0,1,6,7,15, 0,1,2,6,7,8,15, 1,2,6,7,8,9,15, 2,7,8,9,15, 8,9,15,
    4,5,10,11,12,14, 5,10,11,12,13, 11,13,14, 3,12,14, 3,4,10,12,13,
    3,4,5,10,11,13,14};

__device__ __forceinline__ unsigned long long pack2(float lo, float hi) {
    unsigned long long r;
    asm("mov.b64 %0, {%1, %2};" : "=l"(r) : "f"(lo), "f"(hi));
    return r;
}
__device__ __forceinline__ void unpack2(unsigned long long v, float& lo, float& hi) {
    asm("mov.b64 {%0, %1}, %2;" : "=f"(lo), "=f"(hi) : "l"(v));
}
__device__ __forceinline__ void ffma2(unsigned long long& d,
                                      unsigned long long a,
                                      unsigned long long b) {
    asm("fma.rn.f32x2 %0, %1, %2, %0;" : "+l"(d) : "l"(a), "l"(b));
}

// weight smem: float2 pairs, [group][edge_in_group * 30 + ky*6 + kx]
#define WPG 930   // 31 edges * 30 (5 ky * 6 padded kx)

template <int GRP>
__device__ __forceinline__ void conv_group(
    const float* __restrict__ s_in,       // [6][IN_H][IN_W]
    const float2* __restrict__ s_wg,      // this group's weight pairs
    const float* __restrict__ s_b,
    float* __restrict__ out,
    int b, int x0, int oy, int row, int lx)
{
    // local constexpr tables (device-legal; constant-fold under full unroll)
    constexpr int OFF[2][6]  = {{0, 4, 9, 16, 23, 28}, {0, 6, 11, 14, 17, 22}};
    constexpr int CNT[2][6]  = {{4, 5, 7, 7, 5, 3},    {6, 5, 3, 3, 5, 7}};
    constexpr int SLOT[2][31] = {
        {0,3,6,7, 0,1,3,4,7, 0,1,2,3,4,5,7, 1,2,3,4,5,6,7, 2,4,5,6,7, 5,6,7},
        {1,2,3,4,5,7, 2,3,4,5,6, 4,6,7, 0,5,7, 0,1,3,5,6, 0,1,2,3,4,6,7, 0,0}};
    constexpr int OCS[2][8]  = {{0, 1, 2, 6, 7, 8, 9, 15},
                                {3, 4, 5, 10, 11, 12, 13, 14}};

    unsigned long long acc[8][2];
#pragma unroll
    for (int s = 0; s < 8; ++s) {
        float bv = s_b[OCS[GRP][s]];
        acc[s][0] = pack2(bv, bv);
        acc[s][1] = acc[s][0];
    }

#pragma unroll
    for (int ic = 0; ic < 6; ++ic) {
#pragma unroll 1
        for (int ky = 0; ky < 5; ++ky) {
            const float* rp = &s_in[(ic * IN_H + row + ky) * IN_W + lx];
            float4 va = *reinterpret_cast<const float4*>(rp);
            float4 vb = *reinterpret_cast<const float4*>(rp + 4);
            float v[8];
            v[0] = va.x; v[1] = va.y; v[2] = va.z; v[3] = va.w;
            v[4] = vb.x; v[5] = vb.y; v[6] = vb.z; v[7] = vb.w;
            unsigned long long P[7];   // P[k] = {v[k], v[k+1]}
#pragma unroll
            for (int k = 0; k < 7; ++k) P[k] = pack2(v[k], v[k + 1]);

#pragma unroll
            for (int jj = 0; jj < CNT[GRP][ic]; ++jj) {
                const int e = OFF[GRP][ic] + jj;
                const int s = SLOT[GRP][e];
                const float2* wp = &s_wg[e * 30 + ky * 6];
                ulonglong2 w01 = *reinterpret_cast<const ulonglong2*>(wp);
                ulonglong2 w23 = *reinterpret_cast<const ulonglong2*>(wp + 2);
                unsigned long long w4 =
                    *reinterpret_cast<const unsigned long long*>(wp + 4);
                ffma2(acc[s][0], P[0], w01.x);
                ffma2(acc[s][1], P[2], w01.x);
                ffma2(acc[s][0], P[1], w01.y);
                ffma2(acc[s][1], P[3], w01.y);
                ffma2(acc[s][0], P[2], w23.x);
                ffma2(acc[s][1], P[4], w23.x);
                ffma2(acc[s][0], P[3], w23.y);
                ffma2(acc[s][1], P[5], w23.y);
                ffma2(acc[s][0], P[4], w4);
                ffma2(acc[s][1], P[6], w4);
            }
        }
    }

    const int ox = x0 + lx;
    if (ox < OW) {
#pragma unroll
        for (int s = 0; s < 8; ++s) {
            float4 r;
            unpack2(acc[s][0], r.x, r.y);
            unpack2(acc[s][1], r.z, r.w);
            *reinterpret_cast<float4*>(
                out + (((size_t)b * 16 + OCS[GRP][s]) * OH + oy) * OW + ox) = r;
        }
    }
}

__global__ void __launch_bounds__(256, 3)
c3_kernel(const float* __restrict__ x,
          const float* __restrict__ wgt,
          const float* __restrict__ bias,
          float* __restrict__ out)
{
    __shared__ float  s_in[6 * IN_H * IN_W];   // 6336 f = 25344 B
    __shared__ float2 s_w2[2 * WPG];           // 1860 f2 = 14880 B
    __shared__ float  s_b[16];

    const int tid = threadIdx.x;
    const int x0 = blockIdx.x * TILE_W;
    const int y0 = blockIdx.y * TILE_H;
    const int b  = blockIdx.z;

    // ---- input tile (OOB -> 0; only feeds skipped outputs) ----
    const float* xb = x + (size_t)b * 6 * IH * IW;
    for (int i = tid; i < 6 * IN_H * IN_W; i += 256) {
        int c   = i / (IN_H * IN_W);
        int rem = i % (IN_H * IN_W);
        int r   = rem / IN_W;
        int col = rem % IN_W;
        int gx = x0 + col;                   // gy = y0+r < 504+8 = 512 always OK
        float v = 0.0f;
        if (gx < IW) v = __ldg(&xb[(c * IH + y0 + r) * IW + gx]);
        s_in[(c * IN_H + r) * IN_W + col] = v;
    }
    // ---- weights, pre-splatted {w,w}: 60 edges x 25 taps ----
    for (int i = tid; i < 1500; i += 256) {
        int e  = i / 25;
        int k  = i % 25;
        int ky = k / 5, kx = k % 5;
        int ic = E_IC[e], oc = E_OC[e];
        int g  = (e >= 31);
        int eg = e - (g ? 31 : 0);
        float w = __ldg(&wgt[((oc * 6 + ic) * 5 + ky) * 5 + kx]);
        s_w2[g * WPG + eg * 30 + ky * 6 + kx] = make_float2(w, w);
    }
    if (tid < 16) s_b[tid] = __ldg(&bias[tid]);
    __syncthreads();

    const int wid  = tid >> 5;
    const int lane = tid & 31;
    const int row  = wid & 3;        // output row within tile
    const int grp  = wid >> 2;       // oc-group
    const int lx   = lane * 4;
    const int oy   = y0 + row;       // always < 508 (126*4+3 = 507)

    if (grp == 0)
        conv_group<0>(s_in, s_w2,       s_b, out, b, x0, oy, row, lx);
    else
        conv_group<1>(s_in, s_w2 + WPG, s_b, out, b, x0, oy, row, lx);
}

extern "C" void kernel_launch(void* const* d_in, const int* in_sizes, int n_in,
                              void* d_out, int out_size)
{
    const float* x    = (const float*)d_in[0];  // [32,6,512,512]
    const float* wgt  = (const float*)d_in[1];  // [16,6,5,5]
    const float* bias = (const float*)d_in[2];  // [16]
    float* out = (float*)d_out;                 // [32,16,508,508]

    dim3 grid((OW + TILE_W - 1) / TILE_W,       // 4
              OH / TILE_H,                      // 127 (exact)
              32);                              // batch
    c3_kernel<<<grid, 256>>>(x, wgt, bias, out);
}